// round 1
// baseline (speedup 1.0000x reference)
#include <cuda_runtime.h>
#include <cuda_bf16.h>
#include <math.h>
#include <stdint.h>

// ---------------------------------------------------------------------------
// SVM RBF inference: out = tanh(K @ (labels*relu(lambda)) + b)
//   K[b,n] = exp(-(||x_b||^2 + ||s_n||^2 - 2 x_b.s_n)/2)
// B=2048, N=50000, D=256.
// Fused bf16 HMMA GEMM + thresholded exp epilogue (terms with sqdist>=80
// contribute < 1e-17 absolute and are dropped; data distribution puts ALL
// terms far above the threshold, so the MUFU path is cold).
// ---------------------------------------------------------------------------

#define B_ROWS   2048
#define D_DIM    256
#define N_ROWS   50000
#define N_PAD    50048           // 391 * 128
#define N_TILES  391
#define BM       128
#define BN       128
#define THREADS  256
#define NSPLIT   18
#define THRESH   80.0f

#define A_STRIDE 528             // bytes per A row (256 bf16 + 8 pad -> conflict-free LDSM)
#define A_BYTES  (BM * A_STRIDE) // 67584
#define B_STRIDE 80              // bytes per B row (32 bf16 + 8 pad)
#define B_STAGE  (BN * B_STRIDE) // 10240
#define SMEM_BYTES (A_BYTES + 2 * B_STAGE) // 88064

// Scratch (static device arrays: no allocation in kernel_launch)
__device__ __align__(256) __nv_bfloat16 g_xb[B_ROWS * D_DIM];
__device__ __align__(256) __nv_bfloat16 g_sb[N_PAD * D_DIM];
__device__ __align__(256) float g_x2[B_ROWS];
__device__ __align__(256) float g_s2[N_PAD];
__device__ __align__(256) float g_w[N_PAD];
__device__ __align__(256) float g_acc[B_ROWS];

// ---------------------------------------------------------------------------
// Prep kernels
// ---------------------------------------------------------------------------
__global__ void prep_x(const float* __restrict__ x) {
    int row = blockIdx.x;
    int t = threadIdx.x;                       // 64 threads, 4 floats each
    float4 v = reinterpret_cast<const float4*>(x + (size_t)row * D_DIM)[t];
    float ss = v.x * v.x + v.y * v.y + v.z * v.z + v.w * v.w;
    __nv_bfloat162* dst = reinterpret_cast<__nv_bfloat162*>(g_xb + (size_t)row * D_DIM);
    dst[2 * t]     = __float22bfloat162_rn(make_float2(v.x, v.y));
    dst[2 * t + 1] = __float22bfloat162_rn(make_float2(v.z, v.w));
    #pragma unroll
    for (int o = 16; o > 0; o >>= 1) ss += __shfl_xor_sync(0xffffffffu, ss, o);
    __shared__ float sred[2];
    if ((t & 31) == 0) sred[t >> 5] = ss;
    __syncthreads();
    if (t == 0) {
        g_x2[row] = sred[0] + sred[1];
        g_acc[row] = 0.0f;
    }
}

__global__ void prep_s(const float* __restrict__ ds,
                       const float* __restrict__ labels,
                       const float* __restrict__ lam) {
    int row = blockIdx.x;
    int t = threadIdx.x;                       // 64 threads
    __nv_bfloat162* dst = reinterpret_cast<__nv_bfloat162*>(g_sb + (size_t)row * D_DIM);
    if (row < N_ROWS) {
        float4 v = reinterpret_cast<const float4*>(ds + (size_t)row * D_DIM)[t];
        float ss = v.x * v.x + v.y * v.y + v.z * v.z + v.w * v.w;
        dst[2 * t]     = __float22bfloat162_rn(make_float2(v.x, v.y));
        dst[2 * t + 1] = __float22bfloat162_rn(make_float2(v.z, v.w));
        #pragma unroll
        for (int o = 16; o > 0; o >>= 1) ss += __shfl_xor_sync(0xffffffffu, ss, o);
        __shared__ float sred[2];
        if ((t & 31) == 0) sred[t >> 5] = ss;
        __syncthreads();
        if (t == 0) {
            g_s2[row] = sred[0] + sred[1];
            g_w[row]  = labels[row] * fmaxf(lam[row], 0.0f);
        }
    } else {
        __nv_bfloat162 z = __float22bfloat162_rn(make_float2(0.0f, 0.0f));
        dst[2 * t] = z;
        dst[2 * t + 1] = z;
        if (t == 0) { g_s2[row] = 1.0e9f; g_w[row] = 0.0f; }
    }
}

// ---------------------------------------------------------------------------
// PTX helpers
// ---------------------------------------------------------------------------
__device__ __forceinline__ void cp16(uint32_t saddr, const void* gaddr) {
    asm volatile("cp.async.cg.shared.global [%0], [%1], 16;\n"
                 :: "r"(saddr), "l"(gaddr));
}
__device__ __forceinline__ void cp_commit() {
    asm volatile("cp.async.commit_group;\n");
}
__device__ __forceinline__ void cp_wait_all() {
    asm volatile("cp.async.wait_group 0;\n");
}
__device__ __forceinline__ void ldsm4(uint32_t& r0, uint32_t& r1, uint32_t& r2, uint32_t& r3,
                                      uint32_t addr) {
    asm volatile("ldmatrix.sync.aligned.m8n8.x4.shared.b16 {%0,%1,%2,%3}, [%4];"
                 : "=r"(r0), "=r"(r1), "=r"(r2), "=r"(r3) : "r"(addr));
}
__device__ __forceinline__ void mma_bf16(float d[4], const uint32_t a[4],
                                         uint32_t b0, uint32_t b1) {
    asm volatile(
        "mma.sync.aligned.m16n8k16.row.col.f32.bf16.bf16.f32 "
        "{%0,%1,%2,%3},{%4,%5,%6,%7},{%8,%9},{%0,%1,%2,%3};"
        : "+f"(d[0]), "+f"(d[1]), "+f"(d[2]), "+f"(d[3])
        : "r"(a[0]), "r"(a[1]), "r"(a[2]), "r"(a[3]), "r"(b0), "r"(b1));
}

// ---------------------------------------------------------------------------
// Main fused kernel
// ---------------------------------------------------------------------------
__global__ void __launch_bounds__(THREADS, 2) svm_main() {
    extern __shared__ char smem[];
    const uint32_t smem_u = (uint32_t)__cvta_generic_to_shared(smem);
    const uint32_t sA = smem_u;
    const uint32_t sB = smem_u + A_BYTES;

    const int tid  = threadIdx.x;
    const int lane = tid & 31;
    const int wid  = tid >> 5;
    const int wm   = wid & 3;   // 4 warps along M (32 rows each)
    const int wn   = wid >> 2;  // 2 warps along N (64 cols each)
    const int bm0  = blockIdx.x * BM;

    // ---- Load A tile (BM x 256 bf16) into SMEM, resident for whole kernel ----
    {
        const __nv_bfloat16* gx = g_xb + (size_t)bm0 * D_DIM;
        #pragma unroll
        for (int i = 0; i < 16; i++) {
            int u = tid + THREADS * i;
            int r = u >> 5, c = u & 31;
            cp16(sA + r * A_STRIDE + c * 16, gx + (size_t)r * D_DIM + c * 8);
        }
    }

    // ---- Hoisted LDSM addresses ----
    uint32_t a_base[2];
    #pragma unroll
    for (int mi = 0; mi < 2; mi++) {
        int r = wm * 32 + mi * 16 + (lane & 15);
        a_base[mi] = sA + r * A_STRIDE + (lane >> 4) * 16;
    }
    uint32_t b_row[4];
    {
        int grp = lane >> 3;
        #pragma unroll
        for (int p = 0; p < 4; p++) {
            int r = wn * 64 + p * 16 + (grp >> 1) * 8 + (lane & 7);
            b_row[p] = (uint32_t)(r * B_STRIDE + (grp & 1) * 16);
        }
    }

    float x2v[2][2];
    #pragma unroll
    for (int mi = 0; mi < 2; mi++) {
        int r = bm0 + wm * 32 + mi * 16 + (lane >> 2);
        x2v[mi][0] = g_x2[r];
        x2v[mi][1] = g_x2[r + 8];
    }

    float rsum[2][2] = {{0.0f, 0.0f}, {0.0f, 0.0f}};

    for (int t = blockIdx.y; t < N_TILES; t += NSPLIT) {
        const int n0 = t * BN;
        const __nv_bfloat16* gs = g_sb + (size_t)n0 * D_DIM;

        // prologue: stage 0 of B (kt = 0)
        #pragma unroll
        for (int i = 0; i < 2; i++) {
            int u = tid + THREADS * i;
            int r = u >> 2, c = u & 3;
            cp16(sB + r * B_STRIDE + c * 16, gs + (size_t)r * D_DIM + c * 8);
        }
        cp_commit();

        float acc[2][8][4];
        #pragma unroll
        for (int mi = 0; mi < 2; mi++)
            #pragma unroll
            for (int ni = 0; ni < 8; ni++)
                #pragma unroll
                for (int j = 0; j < 4; j++) acc[mi][ni][j] = 0.0f;

        #pragma unroll
        for (int kt = 0; kt < 8; kt++) {
            cp_wait_all();
            __syncthreads();
            if (kt < 7) {
                #pragma unroll
                for (int i = 0; i < 2; i++) {
                    int u = tid + THREADS * i;
                    int r = u >> 2, c = u & 3;
                    cp16(sB + ((kt + 1) & 1) * B_STAGE + r * B_STRIDE + c * 16,
                         gs + (size_t)r * D_DIM + (kt + 1) * 32 + c * 8);
                }
                cp_commit();
            }
            const uint32_t stage = sB + (kt & 1) * B_STAGE;
            #pragma unroll
            for (int k16 = 0; k16 < 2; k16++) {
                uint32_t a[2][4];
                #pragma unroll
                for (int mi = 0; mi < 2; mi++)
                    ldsm4(a[mi][0], a[mi][1], a[mi][2], a[mi][3],
                          a_base[mi] + (kt * 4 + 2 * k16) * 16);
                uint32_t bfr[4][4];
                #pragma unroll
                for (int p = 0; p < 4; p++)
                    ldsm4(bfr[p][0], bfr[p][1], bfr[p][2], bfr[p][3],
                          stage + b_row[p] + k16 * 32);
                #pragma unroll
                for (int mi = 0; mi < 2; mi++)
                    #pragma unroll
                    for (int ni = 0; ni < 8; ni++)
                        mma_bf16(acc[mi][ni], a[mi],
                                 bfr[ni >> 1][(ni & 1) * 2],
                                 bfr[ni >> 1][(ni & 1) * 2 + 1]);
            }
        }

        // ---- Epilogue: sqdist threshold + (cold) exp accumulate ----
        #pragma unroll
        for (int ni = 0; ni < 8; ni++) {
            int cb2 = (n0 + wn * 64 + ni * 8) >> 1; // float2 index
            float2 s2v = reinterpret_cast<const float2*>(g_s2)[cb2 + (lane & 3)];
            float2 wv  = reinterpret_cast<const float2*>(g_w)[cb2 + (lane & 3)];
            #pragma unroll
            for (int mi = 0; mi < 2; mi++) {
                #pragma unroll
                for (int h = 0; h < 2; h++) {
                    float c0 = acc[mi][ni][h * 2];
                    float c1 = acc[mi][ni][h * 2 + 1];
                    float sq0 = fmaf(c0, -2.0f, x2v[mi][h] + s2v.x);
                    float sq1 = fmaf(c1, -2.0f, x2v[mi][h] + s2v.y);
                    if (sq0 < THRESH) rsum[mi][h] += __expf(-0.5f * sq0) * wv.x;
                    if (sq1 < THRESH) rsum[mi][h] += __expf(-0.5f * sq1) * wv.y;
                }
            }
        }
    }

    // ---- Row reduction: shfl within quad, atomicAdd per row ----
    #pragma unroll
    for (int mi = 0; mi < 2; mi++) {
        #pragma unroll
        for (int h = 0; h < 2; h++) {
            float v = rsum[mi][h];
            v += __shfl_xor_sync(0xffffffffu, v, 1);
            v += __shfl_xor_sync(0xffffffffu, v, 2);
            if ((lane & 3) == 0) {
                int r = bm0 + wm * 32 + mi * 16 + (lane >> 2) + h * 8;
                atomicAdd(&g_acc[r], v);
            }
        }
    }
}

// ---------------------------------------------------------------------------
// Finalize: out = tanh(acc + b)
// ---------------------------------------------------------------------------
__global__ void finalize(const float* __restrict__ b, float* __restrict__ out) {
    int i = blockIdx.x * blockDim.x + threadIdx.x;
    if (i < B_ROWS) out[i] = tanhf(g_acc[i] + b[0]);
}

// ---------------------------------------------------------------------------
extern "C" void kernel_launch(void* const* d_in, const int* in_sizes, int n_in,
                              void* d_out, int out_size) {
    const float* x      = (const float*)d_in[0];
    const float* ds     = (const float*)d_in[1];
    const float* labels = (const float*)d_in[2];
    const float* lam    = (const float*)d_in[3];
    const float* b      = (const float*)d_in[4];
    float* out = (float*)d_out;
    (void)in_sizes; (void)n_in; (void)out_size;

    cudaFuncSetAttribute(svm_main, cudaFuncAttributeMaxDynamicSharedMemorySize,
                         SMEM_BYTES);

    prep_x<<<B_ROWS, 64>>>(x);
    prep_s<<<N_PAD, 64>>>(ds, labels, lam);

    dim3 grid(B_ROWS / BM, NSPLIT);
    svm_main<<<grid, THREADS, SMEM_BYTES>>>();

    finalize<<<(B_ROWS + 255) / 256, 256>>>(b, out);
}

// round 3
// speedup vs baseline: 1.1444x; 1.1444x over previous
#include <cuda_runtime.h>
#include <cuda_bf16.h>
#include <math.h>
#include <stdint.h>

// ---------------------------------------------------------------------------
// SVM RBF inference: out = tanh(K @ (labels*relu(lambda)) + b)
//   K[b,n] = exp(-(||x_b||^2 + ||s_n||^2 - 2 x_b.s_n)/2),  B=2048, N=50000, D=256
// mma.sync bf16 HMMA (tcgen05 unavailable: harness compiles at base sm_103
// target, 'a'-features rejected). v2: register-level LDSM double buffering +
// continuous cp.async ring (wait_group<1>) + 64-wide B stages.
// Thresholded exp epilogue: min sqdist over data ~130 >> 80, exp path cold.
// ---------------------------------------------------------------------------

#define B_ROWS   2048
#define D_DIM    256
#define N_ROWS   50000
#define N_PAD    50048           // 391 * 128
#define N_TILES  391
#define BM       128
#define BN       128
#define THREADS  256
#define NSPLIT   18
#define THRESH   80.0f

#define A_STRIDE 528             // 256 bf16 + 8 pad  (16*33: conflict-free LDSM)
#define A_BYTES  (BM * A_STRIDE) // 67584
#define B_STRIDE 144             // 64 bf16 + 8 pad   (16*9: conflict-free LDSM)
#define B_STG    (BN * B_STRIDE) // 18432
#define SMEM_BYTES (A_BYTES + 2 * B_STG) // 104448 -> 2 CTAs/SM

// Scratch (static device arrays: no allocation in kernel_launch)
__device__ __align__(256) __nv_bfloat16 g_xb[B_ROWS * D_DIM];
__device__ __align__(256) __nv_bfloat16 g_sb[N_PAD * D_DIM];
__device__ __align__(256) float g_x2[B_ROWS];
__device__ __align__(256) float g_s2[N_PAD];
__device__ __align__(256) float g_w[N_PAD];
__device__ __align__(256) float g_acc[B_ROWS];

// ---------------------------------------------------------------------------
// Prep kernels
// ---------------------------------------------------------------------------
__global__ void prep_x(const float* __restrict__ x) {
    int row = blockIdx.x;
    int t = threadIdx.x;                       // 64 threads, 4 floats each
    float4 v = reinterpret_cast<const float4*>(x + (size_t)row * D_DIM)[t];
    float ss = v.x * v.x + v.y * v.y + v.z * v.z + v.w * v.w;
    __nv_bfloat162* dst = reinterpret_cast<__nv_bfloat162*>(g_xb + (size_t)row * D_DIM);
    dst[2 * t]     = __float22bfloat162_rn(make_float2(v.x, v.y));
    dst[2 * t + 1] = __float22bfloat162_rn(make_float2(v.z, v.w));
    #pragma unroll
    for (int o = 16; o > 0; o >>= 1) ss += __shfl_xor_sync(0xffffffffu, ss, o);
    __shared__ float sred[2];
    if ((t & 31) == 0) sred[t >> 5] = ss;
    __syncthreads();
    if (t == 0) { g_x2[row] = sred[0] + sred[1]; g_acc[row] = 0.0f; }
}

__global__ void prep_s(const float* __restrict__ ds,
                       const float* __restrict__ labels,
                       const float* __restrict__ lam) {
    int row = blockIdx.x;
    int t = threadIdx.x;
    __nv_bfloat162* dst = reinterpret_cast<__nv_bfloat162*>(g_sb + (size_t)row * D_DIM);
    if (row < N_ROWS) {
        float4 v = reinterpret_cast<const float4*>(ds + (size_t)row * D_DIM)[t];
        float ss = v.x * v.x + v.y * v.y + v.z * v.z + v.w * v.w;
        dst[2 * t]     = __float22bfloat162_rn(make_float2(v.x, v.y));
        dst[2 * t + 1] = __float22bfloat162_rn(make_float2(v.z, v.w));
        #pragma unroll
        for (int o = 16; o > 0; o >>= 1) ss += __shfl_xor_sync(0xffffffffu, ss, o);
        __shared__ float sred[2];
        if ((t & 31) == 0) sred[t >> 5] = ss;
        __syncthreads();
        if (t == 0) {
            g_s2[row] = sred[0] + sred[1];
            g_w[row]  = labels[row] * fmaxf(lam[row], 0.0f);
        }
    } else {
        __nv_bfloat162 z = __float22bfloat162_rn(make_float2(0.0f, 0.0f));
        dst[2 * t] = z;
        dst[2 * t + 1] = z;
        if (t == 0) { g_s2[row] = 1.0e9f; g_w[row] = 0.0f; }
    }
}

// ---------------------------------------------------------------------------
// PTX helpers
// ---------------------------------------------------------------------------
__device__ __forceinline__ void cp16(uint32_t saddr, const void* gaddr) {
    asm volatile("cp.async.cg.shared.global [%0], [%1], 16;\n"
                 :: "r"(saddr), "l"(gaddr));
}
__device__ __forceinline__ void cp_commit() {
    asm volatile("cp.async.commit_group;\n");
}
template <int N>
__device__ __forceinline__ void cp_wait() {
    asm volatile("cp.async.wait_group %0;\n" :: "n"(N));
}
__device__ __forceinline__ void ldsm4(uint32_t* r, uint32_t addr) {
    asm volatile("ldmatrix.sync.aligned.m8n8.x4.shared.b16 {%0,%1,%2,%3}, [%4];"
                 : "=r"(r[0]), "=r"(r[1]), "=r"(r[2]), "=r"(r[3]) : "r"(addr));
}
__device__ __forceinline__ void mma_bf16(float d[4], const uint32_t a[4],
                                         uint32_t b0, uint32_t b1) {
    asm volatile(
        "mma.sync.aligned.m16n8k16.row.col.f32.bf16.bf16.f32 "
        "{%0,%1,%2,%3},{%4,%5,%6,%7},{%8,%9},{%0,%1,%2,%3};"
        : "+f"(d[0]), "+f"(d[1]), "+f"(d[2]), "+f"(d[3])
        : "r"(a[0]), "r"(a[1]), "r"(a[2]), "r"(a[3]), "r"(b0), "r"(b1));
}

// ---------------------------------------------------------------------------
// Main fused kernel
// ---------------------------------------------------------------------------
__global__ void __launch_bounds__(THREADS, 2) svm_main() {
    extern __shared__ char smem[];
    uint32_t smem_u;
    asm("{ .reg .u64 t; cvta.to.shared.u64 t, %1; cvt.u32.u64 %0, t; }"
        : "=r"(smem_u) : "l"(smem));
    const uint32_t sA = smem_u;
    const uint32_t sB = smem_u + A_BYTES;

    const int tid  = threadIdx.x;
    const int lane = tid & 31;
    const int wid  = tid >> 5;
    const int wm   = wid & 3;   // 4 warps along M (32 rows each)
    const int wn   = wid >> 2;  // 2 warps along N (64 cols each)
    const int bm0  = blockIdx.x * BM;
    const int split = blockIdx.y;

    // ---- Load A tile (BM x 256 bf16), resident for whole kernel ----
    {
        const __nv_bfloat16* gx = g_xb + (size_t)bm0 * D_DIM;
        #pragma unroll
        for (int i = 0; i < 16; i++) {
            int u = tid + THREADS * i;
            int r = u >> 5, c = u & 31;
            cp16(sA + r * A_STRIDE + c * 16, gx + (size_t)r * D_DIM + c * 8);
        }
        cp_commit();                 // group gA
    }

    // ---- Hoisted LDSM addresses ----
    uint32_t a_base[2];
    #pragma unroll
    for (int mi = 0; mi < 2; mi++) {
        int r = wm * 32 + mi * 16 + (lane & 15);
        a_base[mi] = sA + r * A_STRIDE + (lane >> 4) * 16;
    }
    uint32_t b_row[4];
    {
        int grp = lane >> 3;
        #pragma unroll
        for (int p = 0; p < 4; p++) {
            int r = wn * 64 + p * 16 + (grp >> 1) * 8 + (lane & 7);
            b_row[p] = (uint32_t)(r * B_STRIDE + (grp & 1) * 16);
        }
    }

    float x2v[2][2];
    #pragma unroll
    for (int mi = 0; mi < 2; mi++) {
        int r = bm0 + wm * 32 + mi * 16 + (lane >> 2);
        x2v[mi][0] = g_x2[r];
        x2v[mi][1] = g_x2[r + 8];
    }

    const int ntiles = (N_TILES - split + NSPLIT - 1) / NSPLIT;
    const int S = ntiles * 4;       // total 64-K stages

    // B stage loader: stage buffer `buf`, tile row base t0, k-chunk kc (64 cols)
    auto load_b = [&](int buf, int t0, int kc) {
        const __nv_bfloat16* gs = g_sb + (size_t)t0 * BN * D_DIM + kc * 64;
        const uint32_t base = sB + buf * B_STG;
        #pragma unroll
        for (int i = 0; i < 4; i++) {
            int u = tid + THREADS * i;          // 0..1023 (16B chunks)
            int r = u >> 3, c = u & 7;          // row, 16B chunk within 128B
            cp16(base + r * B_STRIDE + c * 16, gs + (size_t)r * D_DIM + c * 8);
        }
    };

    // ---- Preload stages 0 and 1 of first tile ----
    load_b(0, split, 0); cp_commit();           // g0
    load_b(1, split, 1); cp_commit();           // g1

    float rsum[2][2] = {{0.0f, 0.0f}, {0.0f, 0.0f}};

    int t = split;
    for (int ti = 0; ti < ntiles; ti++, t += NSPLIT) {
        float acc[2][8][4];
        #pragma unroll
        for (int mi = 0; mi < 2; mi++)
            #pragma unroll
            for (int ni = 0; ni < 8; ni++)
                #pragma unroll
                for (int j = 0; j < 4; j++) acc[mi][ni][j] = 0.0f;

        #pragma unroll
        for (int kc = 0; kc < 4; kc++) {
            // stage s = ti*4 + kc lives in buffer kc&1; group g_s committed.
            cp_wait<1>();            // all groups except newest complete -> g_s done
            __syncthreads();         // cross-thread visibility

            const uint32_t stg = sB + (kc & 1) * B_STG;

            // ---- register-double-buffered LDSM + MMA over 4 k16 steps ----
            uint32_t a[2][2][4], b[2][4][4];
            #pragma unroll
            for (int mi = 0; mi < 2; mi++)
                ldsm4(a[0][mi], a_base[mi] + (kc * 4 + 0) * 32);
            #pragma unroll
            for (int p = 0; p < 4; p++)
                ldsm4(b[0][p], stg + b_row[p] + 0 * 32);

            #pragma unroll
            for (int j = 0; j < 4; j++) {
                const int cur = j & 1, nxt = cur ^ 1;
                if (j < 3) {
                    #pragma unroll
                    for (int mi = 0; mi < 2; mi++)
                        ldsm4(a[nxt][mi], a_base[mi] + (kc * 4 + j + 1) * 32);
                    #pragma unroll
                    for (int p = 0; p < 4; p++)
                        ldsm4(b[nxt][p], stg + b_row[p] + (j + 1) * 32);
                }
                #pragma unroll
                for (int mi = 0; mi < 2; mi++)
                    #pragma unroll
                    for (int ni = 0; ni < 8; ni++)
                        mma_bf16(acc[mi][ni], a[cur][mi],
                                 b[cur][ni >> 1][(ni & 1) * 2],
                                 b[cur][ni >> 1][(ni & 1) * 2 + 1]);
            }

            __syncthreads();         // all warps done reading buffer kc&1

            // issue load for stage s+2 into the buffer just freed
            const int s2 = ti * 4 + kc + 2;
            if (s2 < S) {
                const int tt = split + (s2 >> 2) * NSPLIT;
                load_b(kc & 1, tt, s2 & 3);
            }
            cp_commit();             // always commit (empty group near the end)
        }

        // ---- Epilogue: sqdist threshold + (cold) exp accumulate ----
        const int n0 = t * BN;
        #pragma unroll
        for (int ni = 0; ni < 8; ni++) {
            int cb2 = (n0 + wn * 64 + ni * 8) >> 1; // float2 index
            float2 s2v = reinterpret_cast<const float2*>(g_s2)[cb2 + (lane & 3)];
            float2 wv  = reinterpret_cast<const float2*>(g_w)[cb2 + (lane & 3)];
            #pragma unroll
            for (int mi = 0; mi < 2; mi++) {
                #pragma unroll
                for (int h = 0; h < 2; h++) {
                    float c0 = acc[mi][ni][h * 2];
                    float c1 = acc[mi][ni][h * 2 + 1];
                    float sq0 = fmaf(c0, -2.0f, x2v[mi][h] + s2v.x);
                    float sq1 = fmaf(c1, -2.0f, x2v[mi][h] + s2v.y);
                    if (sq0 < THRESH) rsum[mi][h] += __expf(-0.5f * sq0) * wv.x;
                    if (sq1 < THRESH) rsum[mi][h] += __expf(-0.5f * sq1) * wv.y;
                }
            }
        }
    }

    // ---- Row reduction: shfl within quad, atomicAdd per row ----
    #pragma unroll
    for (int mi = 0; mi < 2; mi++) {
        #pragma unroll
        for (int h = 0; h < 2; h++) {
            float v = rsum[mi][h];
            v += __shfl_xor_sync(0xffffffffu, v, 1);
            v += __shfl_xor_sync(0xffffffffu, v, 2);
            if ((lane & 3) == 0) {
                int r = bm0 + wm * 32 + mi * 16 + (lane >> 2) + h * 8;
                atomicAdd(&g_acc[r], v);
            }
        }
    }
}

// ---------------------------------------------------------------------------
// Finalize: out = tanh(acc + b)
// ---------------------------------------------------------------------------
__global__ void finalize(const float* __restrict__ b, float* __restrict__ out) {
    int i = blockIdx.x * blockDim.x + threadIdx.x;
    if (i < B_ROWS) out[i] = tanhf(g_acc[i] + b[0]);
}

// ---------------------------------------------------------------------------
extern "C" void kernel_launch(void* const* d_in, const int* in_sizes, int n_in,
                              void* d_out, int out_size) {
    const float* x      = (const float*)d_in[0];
    const float* ds     = (const float*)d_in[1];
    const float* labels = (const float*)d_in[2];
    const float* lam    = (const float*)d_in[3];
    const float* b      = (const float*)d_in[4];
    float* out = (float*)d_out;
    (void)in_sizes; (void)n_in; (void)out_size;

    cudaFuncSetAttribute(svm_main, cudaFuncAttributeMaxDynamicSharedMemorySize,
                         SMEM_BYTES);

    prep_x<<<B_ROWS, 64>>>(x);
    prep_s<<<N_PAD, 64>>>(ds, labels, lam);

    dim3 grid(B_ROWS / BM, NSPLIT);
    svm_main<<<grid, THREADS, SMEM_BYTES>>>();

    finalize<<<(B_ROWS + 255) / 256, 256>>>(b, out);
}

// round 4
// speedup vs baseline: 1.9730x; 1.7240x over previous
#include <cuda_runtime.h>
#include <cuda_fp16.h>
#include <math.h>
#include <stdint.h>

// ---------------------------------------------------------------------------
// SVM RBF inference: out = tanh(K @ (labels*relu(lambda)) + b)
//   K[b,n] = exp(-(||x_b||^2+||s_n||^2-2 x_b.s_n)/2), B=2048, N=50000, D=256
// v3: K-truncated screening GEMM (first 64 dims, fp16 in / fp16 acc HMMA)
//     gives a LOWER BOUND on sqdist; terms with LB>=50 contribute < 1e-11
//     total and are skipped. Rare candidates (P ~ 3e-6/pair for N(0,1) data)
//     take an inline exact fp32 256-dim fixup -> correct for ANY input.
//     Legacy mma.sync pipe on sm_103 saturates ~512 MAC/cyc/SM (measured
//     R1/R3), so we cut MACs 4x instead of fighting the pipe.
// ---------------------------------------------------------------------------

#define B_ROWS   2048
#define D_DIM    256
#define D_H      64              // screening dims
#define N_ROWS   50000
#define N_PAD    50176           // 392 * 128
#define N_TILES  392
#define BM       128
#define BN       128
#define THREADS  256
#define NSPLIT   24
#define T_FIX    50.0f

#define A_STRIDE 144             // 64 fp16 + 8 pad (9*16B: conflict-free LDSM)
#define A_BYTES  (BM * A_STRIDE) // 18432
#define B_STG    (BN * A_STRIDE) // 18432
#define SMEM_BYTES (A_BYTES + 2 * B_STG) // 55296 -> 3 CTAs/SM

// Scratch (static device arrays: no allocation anywhere)
__device__ __align__(256) __half  g_xh[B_ROWS * D_H];
__device__ __align__(256) __half  g_sh[N_PAD * D_H];
__device__ __align__(256) float   g_x2h[B_ROWS];   // ||x[0:64]||^2
__device__ __align__(256) float2  g_s2w[N_PAD];    // {||s[0:64]||^2, w}
__device__ __align__(256) float   g_acc[B_ROWS];

// ---------------------------------------------------------------------------
// Prep: warp per row, first 64 dims only
// ---------------------------------------------------------------------------
__global__ void prep_x(const float* __restrict__ x) {
    int lane = threadIdx.x & 31, wid = threadIdx.x >> 5;
    int row = blockIdx.x * 8 + wid;
    float2 v = reinterpret_cast<const float2*>(x + (size_t)row * D_DIM)[lane];
    reinterpret_cast<__half2*>(g_xh + (size_t)row * D_H)[lane] = __float22half2_rn(v);
    float ss = v.x * v.x + v.y * v.y;
    #pragma unroll
    for (int o = 16; o > 0; o >>= 1) ss += __shfl_xor_sync(0xffffffffu, ss, o);
    if (lane == 0) { g_x2h[row] = ss; g_acc[row] = 0.0f; }
}

__global__ void prep_s(const float* __restrict__ ds,
                       const float* __restrict__ labels,
                       const float* __restrict__ lam) {
    int lane = threadIdx.x & 31, wid = threadIdx.x >> 5;
    int row = blockIdx.x * 8 + wid;
    if (row < N_ROWS) {
        float2 v = reinterpret_cast<const float2*>(ds + (size_t)row * D_DIM)[lane];
        reinterpret_cast<__half2*>(g_sh + (size_t)row * D_H)[lane] = __float22half2_rn(v);
        float ss = v.x * v.x + v.y * v.y;
        #pragma unroll
        for (int o = 16; o > 0; o >>= 1) ss += __shfl_xor_sync(0xffffffffu, ss, o);
        if (lane == 0) {
            float w = labels[row] * fmaxf(lam[row], 0.0f);
            g_s2w[row] = make_float2(ss, w);
        }
    } else {
        reinterpret_cast<__half2*>(g_sh + (size_t)row * D_H)[lane] =
            __float22half2_rn(make_float2(0.0f, 0.0f));
        if (lane == 0) g_s2w[row] = make_float2(1.0e9f, 0.0f);
    }
}

// ---------------------------------------------------------------------------
// PTX helpers
// ---------------------------------------------------------------------------
__device__ __forceinline__ void cp16(uint32_t saddr, const void* gaddr) {
    asm volatile("cp.async.cg.shared.global [%0], [%1], 16;\n"
                 :: "r"(saddr), "l"(gaddr));
}
__device__ __forceinline__ void cp_commit() {
    asm volatile("cp.async.commit_group;\n");
}
template <int N>
__device__ __forceinline__ void cp_wait() {
    asm volatile("cp.async.wait_group %0;\n" :: "n"(N));
}
__device__ __forceinline__ void ldsm4(uint32_t* r, uint32_t addr) {
    asm volatile("ldmatrix.sync.aligned.m8n8.x4.shared.b16 {%0,%1,%2,%3}, [%4];"
                 : "=r"(r[0]), "=r"(r[1]), "=r"(r[2]), "=r"(r[3]) : "r"(addr));
}
// f16 in, f16 acc: D/C are 2 regs (f16x2)
__device__ __forceinline__ void mma_f16(uint32_t& d0, uint32_t& d1,
                                        const uint32_t a[4],
                                        uint32_t b0, uint32_t b1) {
    asm volatile(
        "mma.sync.aligned.m16n8k16.row.col.f16.f16.f16.f16 "
        "{%0,%1},{%2,%3,%4,%5},{%6,%7},{%0,%1};"
        : "+r"(d0), "+r"(d1)
        : "r"(a[0]), "r"(a[1]), "r"(a[2]), "r"(a[3]), "r"(b0), "r"(b1));
}

// Cold path: exact 256-dim fp32 squared distance from the ORIGINAL inputs.
__device__ __noinline__ float exact_sqdist(const float* __restrict__ xr,
                                           const float* __restrict__ sr) {
    float d2 = 0.0f;
    #pragma unroll 1
    for (int i = 0; i < D_DIM / 4; i++) {
        float4 a = reinterpret_cast<const float4*>(xr)[i];
        float4 b = reinterpret_cast<const float4*>(sr)[i];
        float dx = a.x - b.x, dy = a.y - b.y, dz = a.z - b.z, dw = a.w - b.w;
        d2 += dx * dx + dy * dy + dz * dz + dw * dw;
    }
    return d2;
}

// ---------------------------------------------------------------------------
// Main fused kernel
// ---------------------------------------------------------------------------
__global__ void __launch_bounds__(THREADS, 3)
svm_main(const float* __restrict__ xp, const float* __restrict__ sp) {
    extern __shared__ char smem[];
    uint32_t smem_u;
    asm("{ .reg .u64 t; cvta.to.shared.u64 t, %1; cvt.u32.u64 %0, t; }"
        : "=r"(smem_u) : "l"(smem));
    const uint32_t sA = smem_u;
    const uint32_t sB = smem_u + A_BYTES;

    const int tid  = threadIdx.x;
    const int lane = tid & 31;
    const int wid  = tid >> 5;
    const int wm   = wid & 3;   // 4 warps along M (32 rows each)
    const int wn   = wid >> 2;  // 2 warps along N (64 cols each)
    const int bm0  = blockIdx.x * BM;
    const int split = blockIdx.y;

    // ---- A tile load (128 rows x 64 fp16), resident ----
    {
        const __half* gx = g_xh + (size_t)bm0 * D_H;
        #pragma unroll
        for (int i = 0; i < 4; i++) {
            int u = tid + THREADS * i;      // 0..1023 16B chunks
            int r = u >> 3, c = u & 7;
            cp16(sA + r * A_STRIDE + c * 16, gx + (size_t)r * D_H + c * 8);
        }
        cp_commit();                        // GA
    }

    // B tile loader
    auto load_b = [&](int buf, int t0) {
        const __half* gs = g_sh + (size_t)t0 * BN * D_H;
        const uint32_t base = sB + buf * B_STG;
        #pragma unroll
        for (int i = 0; i < 4; i++) {
            int u = tid + THREADS * i;
            int r = u >> 3, c = u & 7;
            cp16(base + r * A_STRIDE + c * 16, gs + (size_t)r * D_H + c * 8);
        }
    };

    const int ntiles = (N_TILES - split + NSPLIT - 1) / NSPLIT;
    // prologue: tiles 0 and 1
    load_b(0, split); cp_commit();          // G0
    if (ntiles > 1) load_b(1, split + NSPLIT);
    cp_commit();                            // G1 (possibly empty)

    // ---- hoisted LDSM addresses ----
    uint32_t a_base[2];
    #pragma unroll
    for (int mi = 0; mi < 2; mi++) {
        int r = wm * 32 + mi * 16 + (lane & 15);
        a_base[mi] = sA + r * A_STRIDE + (lane >> 4) * 16;
    }
    uint32_t b_row[4];
    {
        int grp = lane >> 3;
        #pragma unroll
        for (int p = 0; p < 4; p++) {
            int r = wn * 64 + p * 16 + (grp >> 1) * 8 + (lane & 7);
            b_row[p] = (uint32_t)(r * A_STRIDE + (grp & 1) * 16);
        }
    }

    float x2v[2][2];
    #pragma unroll
    for (int mi = 0; mi < 2; mi++) {
        int r = bm0 + wm * 32 + mi * 16 + (lane >> 2);
        x2v[mi][0] = g_x2h[r];
        x2v[mi][1] = g_x2h[r + 8];
    }

    float rsum[2][2] = {{0.0f, 0.0f}, {0.0f, 0.0f}};

    int t = split;
    for (int ti = 0; ti < ntiles; ti++, t += NSPLIT) {
        cp_wait<1>();            // tile ti's group complete (ti+1 may be in flight)
        __syncthreads();

        const int buf = ti & 1;
        const uint32_t stg = sB + buf * B_STG;

        uint32_t acc[2][8][2];
        #pragma unroll
        for (int mi = 0; mi < 2; mi++)
            #pragma unroll
            for (int ni = 0; ni < 8; ni++) { acc[mi][ni][0] = 0u; acc[mi][ni][1] = 0u; }

        #pragma unroll
        for (int j = 0; j < 4; j++) {        // 4 k16 steps over D_H=64
            uint32_t a[2][4];
            ldsm4(a[0], a_base[0] + j * 32);
            ldsm4(a[1], a_base[1] + j * 32);
            #pragma unroll
            for (int p = 0; p < 4; p++) {
                uint32_t bb[4];
                ldsm4(bb, stg + b_row[p] + j * 32);
                mma_f16(acc[0][2 * p][0],     acc[0][2 * p][1],     a[0], bb[0], bb[1]);
                mma_f16(acc[0][2 * p + 1][0], acc[0][2 * p + 1][1], a[0], bb[2], bb[3]);
                mma_f16(acc[1][2 * p][0],     acc[1][2 * p][1],     a[1], bb[0], bb[1]);
                mma_f16(acc[1][2 * p + 1][0], acc[1][2 * p + 1][1], a[1], bb[2], bb[3]);
            }
        }

        __syncthreads();         // all warps done reading buf
        if (ti + 2 < ntiles) load_b(buf, t + 2 * NSPLIT);
        cp_commit();             // always commit (keeps wait<1> bookkeeping exact)

        // ---- epilogue: LB screening; exact fixup is warp-coherently cold ----
        const int n0 = t * BN;
        #pragma unroll
        for (int ni = 0; ni < 8; ni++) {
            const int nc = n0 + wn * 64 + ni * 8 + 2 * (lane & 3);
            float4 sv = *reinterpret_cast<const float4*>(g_s2w + nc); // s2h0,w0,s2h1,w1
            #pragma unroll
            for (int mi = 0; mi < 2; mi++) {
                #pragma unroll
                for (int h = 0; h < 2; h++) {
                    __half2 hv = *reinterpret_cast<__half2*>(&acc[mi][ni][h]);
                    float2 c = __half22float2(hv);
                    const float x2 = x2v[mi][h];
                    float lb0 = fmaf(c.x, -2.0f, x2 + sv.x);
                    float lb1 = fmaf(c.y, -2.0f, x2 + sv.z);
                    if (__builtin_expect(lb0 < T_FIX && sv.y != 0.0f, 0)) {
                        int r = bm0 + wm * 32 + mi * 16 + (lane >> 2) + 8 * h;
                        float d2 = exact_sqdist(xp + (size_t)r * D_DIM,
                                                sp + (size_t)nc * D_DIM);
                        rsum[mi][h] += __expf(-0.5f * d2) * sv.y;
                    }
                    if (__builtin_expect(lb1 < T_FIX && sv.w != 0.0f, 0)) {
                        int r = bm0 + wm * 32 + mi * 16 + (lane >> 2) + 8 * h;
                        float d2 = exact_sqdist(xp + (size_t)r * D_DIM,
                                                sp + (size_t)(nc + 1) * D_DIM);
                        rsum[mi][h] += __expf(-0.5f * d2) * sv.w;
                    }
                }
            }
        }
    }

    // ---- row reduction: shfl within quad, one atomic per row per CTA ----
    #pragma unroll
    for (int mi = 0; mi < 2; mi++) {
        #pragma unroll
        for (int h = 0; h < 2; h++) {
            float v = rsum[mi][h];
            v += __shfl_xor_sync(0xffffffffu, v, 1);
            v += __shfl_xor_sync(0xffffffffu, v, 2);
            if ((lane & 3) == 0) {
                int r = bm0 + wm * 32 + mi * 16 + (lane >> 2) + h * 8;
                atomicAdd(&g_acc[r], v);
            }
        }
    }
}

// ---------------------------------------------------------------------------
__global__ void finalize(const float* __restrict__ b, float* __restrict__ out) {
    int i = blockIdx.x * blockDim.x + threadIdx.x;
    if (i < B_ROWS) out[i] = tanhf(g_acc[i] + b[0]);
}

// ---------------------------------------------------------------------------
extern "C" void kernel_launch(void* const* d_in, const int* in_sizes, int n_in,
                              void* d_out, int out_size) {
    const float* x      = (const float*)d_in[0];
    const float* ds     = (const float*)d_in[1];
    const float* labels = (const float*)d_in[2];
    const float* lam    = (const float*)d_in[3];
    const float* b      = (const float*)d_in[4];
    float* out = (float*)d_out;
    (void)in_sizes; (void)n_in; (void)out_size;

    cudaFuncSetAttribute(svm_main, cudaFuncAttributeMaxDynamicSharedMemorySize,
                         SMEM_BYTES);

    prep_x<<<B_ROWS / 8, 256>>>(x);
    prep_s<<<N_PAD / 8, 256>>>(ds, labels, lam);

    dim3 grid(B_ROWS / BM, NSPLIT);
    svm_main<<<grid, THREADS, SMEM_BYTES>>>(x, ds);

    finalize<<<(B_ROWS + 255) / 256, 256>>>(b, out);
}

// round 5
// speedup vs baseline: 2.5070x; 1.2706x over previous
#include <cuda_runtime.h>
#include <cuda_fp16.h>
#include <math.h>
#include <stdint.h>

// ---------------------------------------------------------------------------
// SVM RBF inference: out = tanh(K @ (labels*relu(lambda)) + b)
//   K[b,n] = exp(-(||x_b||^2+||s_n||^2-2 x_b.s_n)/2), B=2048, N=50000, D=256
// v4: AUGMENTED screening GEMM. 64-wide fp16 operands where dims 0..61 are
//     the raw data and dims 62,63 encode the norms:
//       x' = [x0..x61, -0.5*||x||62^2, 1],  s' = [s0..s61, 1, -0.5*||s||62^2]
//     so the f16-acc HMMA output is exactly -0.5 * LB, where LB = 62-dim
//     sqdist, a LOWER BOUND of the 256-dim sqdist. Terms with LB >= 50
//     contribute < 1e-11 in total and are skipped; hot epilogue is ONE HMAX2
//     per 2 elements. Rare candidates (P ~ 2-5e-4, N(0,1) data) take an exact
//     fp32 256-dim fixup from the original inputs -> correct for ANY input.
//     finalize (tanh) folded into the last-arriving CTA; 2 launches total.
// ---------------------------------------------------------------------------

#define B_ROWS   2048
#define D_DIM    256
#define D_H      64              // screening K (62 data dims + 2 aug)
#define N_ROWS   50000
#define N_PAD    50176           // 392 * 128
#define N_TILES  392
#define BM       128
#define BN       128
#define THREADS  256
#define NSPLIT   27
#define GRID_X   (B_ROWS / BM)
#define TOTAL_CTAS (GRID_X * NSPLIT)
#define TACC     (-25.5f)        // acc = -0.5*LB; rescan if acc > TACC

#define A_STRIDE 144             // 64 fp16 + 8 pad (9*16B: conflict-free LDSM)
#define A_BYTES  (BM * A_STRIDE) // 18432
#define B_STG    (BN * A_STRIDE) // 18432
#define SMEM_BYTES (A_BYTES + 2 * B_STG) // 55296 -> 3 CTAs/SM

// Scratch (static device arrays: no allocation anywhere)
__device__ __align__(256) __half g_xh[B_ROWS * D_H];
__device__ __align__(256) __half g_sh[N_PAD * D_H];
__device__ __align__(256) float  g_w[N_PAD];
__device__ __align__(256) float  g_acc[B_ROWS];
__device__ int g_done;           // 0 at start of every call (self-resetting)

// ---------------------------------------------------------------------------
// Merged prep: one warp per row; builds augmented fp16 rows + w; zeroes acc.
// ---------------------------------------------------------------------------
__global__ void prep(const float* __restrict__ x,
                     const float* __restrict__ ds,
                     const float* __restrict__ labels,
                     const float* __restrict__ lam) {
    const int lane = threadIdx.x & 31;
    const int gw = blockIdx.x * 8 + (threadIdx.x >> 5);
    if (gw < B_ROWS) {
        const int row = gw;
        float2 v = reinterpret_cast<const float2*>(x + (size_t)row * D_DIM)[lane];
        float ss = (lane < 31) ? (v.x * v.x + v.y * v.y) : 0.0f;
        #pragma unroll
        for (int o = 16; o > 0; o >>= 1) ss += __shfl_xor_sync(0xffffffffu, ss, o);
        __half2 out = (lane < 31) ? __float22half2_rn(v)
                                  : __floats2half2_rn(-0.5f * ss, 1.0f);
        reinterpret_cast<__half2*>(g_xh + (size_t)row * D_H)[lane] = out;
        if (lane == 0) g_acc[row] = 0.0f;
    } else {
        const int row = gw - B_ROWS;
        if (row >= N_PAD) return;
        if (row < N_ROWS) {
            float2 v = reinterpret_cast<const float2*>(ds + (size_t)row * D_DIM)[lane];
            float ss = (lane < 31) ? (v.x * v.x + v.y * v.y) : 0.0f;
            #pragma unroll
            for (int o = 16; o > 0; o >>= 1) ss += __shfl_xor_sync(0xffffffffu, ss, o);
            __half2 out = (lane < 31) ? __float22half2_rn(v)
                                      : __floats2half2_rn(1.0f, -0.5f * ss);
            reinterpret_cast<__half2*>(g_sh + (size_t)row * D_H)[lane] = out;
            if (lane == 0) g_w[row] = labels[row] * fmaxf(lam[row], 0.0f);
        } else {
            __half2 out = (lane < 31) ? __floats2half2_rn(0.0f, 0.0f)
                                      : __floats2half2_rn(1.0f, -30000.0f);
            reinterpret_cast<__half2*>(g_sh + (size_t)row * D_H)[lane] = out;
            if (lane == 0) g_w[row] = 0.0f;
        }
    }
}

// ---------------------------------------------------------------------------
// PTX helpers
// ---------------------------------------------------------------------------
__device__ __forceinline__ void cp16(uint32_t saddr, const void* gaddr) {
    asm volatile("cp.async.cg.shared.global [%0], [%1], 16;\n"
                 :: "r"(saddr), "l"(gaddr));
}
__device__ __forceinline__ void cp_commit() {
    asm volatile("cp.async.commit_group;\n");
}
template <int N>
__device__ __forceinline__ void cp_wait() {
    asm volatile("cp.async.wait_group %0;\n" :: "n"(N));
}
__device__ __forceinline__ void ldsm4(uint32_t* r, uint32_t addr) {
    asm volatile("ldmatrix.sync.aligned.m8n8.x4.shared.b16 {%0,%1,%2,%3}, [%4];"
                 : "=r"(r[0]), "=r"(r[1]), "=r"(r[2]), "=r"(r[3]) : "r"(addr));
}
__device__ __forceinline__ void mma_f16(uint32_t& d0, uint32_t& d1,
                                        const uint32_t a[4],
                                        uint32_t b0, uint32_t b1) {
    asm volatile(
        "mma.sync.aligned.m16n8k16.row.col.f16.f16.f16.f16 "
        "{%0,%1},{%2,%3,%4,%5},{%6,%7},{%0,%1};"
        : "+r"(d0), "+r"(d1)
        : "r"(a[0]), "r"(a[1]), "r"(a[2]), "r"(a[3]), "r"(b0), "r"(b1));
}

// Cold path: exact 256-dim fp32 squared distance from the ORIGINAL inputs.
__device__ __noinline__ float exact_sqdist(const float* __restrict__ xr,
                                           const float* __restrict__ sr) {
    float d2 = 0.0f;
    #pragma unroll 1
    for (int i = 0; i < D_DIM / 4; i++) {
        float4 a = reinterpret_cast<const float4*>(xr)[i];
        float4 b = reinterpret_cast<const float4*>(sr)[i];
        float dx = a.x - b.x, dy = a.y - b.y, dz = a.z - b.z, dw = a.w - b.w;
        d2 += dx * dx + dy * dy + dz * dz + dw * dw;
    }
    return d2;
}

// ---------------------------------------------------------------------------
// Main fused kernel (GEMM + screening epilogue + folded tanh finalize)
// ---------------------------------------------------------------------------
__global__ void __launch_bounds__(THREADS, 3)
svm_main(const float* __restrict__ xp, const float* __restrict__ sp,
         const float* __restrict__ bb, float* __restrict__ out) {
    extern __shared__ char smem[];
    uint32_t smem_u;
    asm("{ .reg .u64 t; cvta.to.shared.u64 t, %1; cvt.u32.u64 %0, t; }"
        : "=r"(smem_u) : "l"(smem));
    const uint32_t sA = smem_u;
    const uint32_t sB = smem_u + A_BYTES;

    const int tid  = threadIdx.x;
    const int lane = tid & 31;
    const int wid  = tid >> 5;
    const int wm   = wid & 3;   // 4 warps along M (32 rows each)
    const int wn   = wid >> 2;  // 2 warps along N (64 cols each)
    const int bm0  = blockIdx.x * BM;
    const int split = blockIdx.y;

    // ---- A tile load (128 rows x 64 fp16), resident ----
    {
        const __half* gx = g_xh + (size_t)bm0 * D_H;
        #pragma unroll
        for (int i = 0; i < 4; i++) {
            int u = tid + THREADS * i;      // 0..1023 16B chunks
            int r = u >> 3, c = u & 7;
            cp16(sA + r * A_STRIDE + c * 16, gx + (size_t)r * D_H + c * 8);
        }
        cp_commit();                        // GA
    }

    auto load_b = [&](int buf, int t0) {
        const __half* gs = g_sh + (size_t)t0 * BN * D_H;
        const uint32_t base = sB + buf * B_STG;
        #pragma unroll
        for (int i = 0; i < 4; i++) {
            int u = tid + THREADS * i;
            int r = u >> 3, c = u & 7;
            cp16(base + r * A_STRIDE + c * 16, gs + (size_t)r * D_H + c * 8);
        }
    };

    const int ntiles = (N_TILES - split + NSPLIT - 1) / NSPLIT;
    load_b(0, split); cp_commit();          // G0
    if (ntiles > 1) load_b(1, split + NSPLIT);
    cp_commit();                            // G1 (possibly empty)

    // ---- hoisted LDSM addresses ----
    uint32_t a_base[2];
    #pragma unroll
    for (int mi = 0; mi < 2; mi++) {
        int r = wm * 32 + mi * 16 + (lane & 15);
        a_base[mi] = sA + r * A_STRIDE + (lane >> 4) * 16;
    }
    uint32_t b_row[4];
    {
        int grp = lane >> 3;
        #pragma unroll
        for (int p = 0; p < 4; p++) {
            int r = wn * 64 + p * 16 + (grp >> 1) * 8 + (lane & 7);
            b_row[p] = (uint32_t)(r * A_STRIDE + (grp & 1) * 16);
        }
    }

    float rsum[2][2] = {{0.0f, 0.0f}, {0.0f, 0.0f}};

    int t = split;
    for (int ti = 0; ti < ntiles; ti++, t += NSPLIT) {
        cp_wait<1>();            // tile ti's group complete (ti+1 may be in flight)
        __syncthreads();

        const int buf = ti & 1;
        const uint32_t stg = sB + buf * B_STG;

        uint32_t acc[2][8][2];
        #pragma unroll
        for (int mi = 0; mi < 2; mi++)
            #pragma unroll
            for (int ni = 0; ni < 8; ni++) { acc[mi][ni][0] = 0u; acc[mi][ni][1] = 0u; }

        #pragma unroll
        for (int j = 0; j < 4; j++) {        // 4 k16 steps over D_H=64
            uint32_t a[2][4];
            ldsm4(a[0], a_base[0] + j * 32);
            ldsm4(a[1], a_base[1] + j * 32);
            #pragma unroll
            for (int p = 0; p < 4; p++) {
                uint32_t bbq[4];
                ldsm4(bbq, stg + b_row[p] + j * 32);
                mma_f16(acc[0][2 * p][0],     acc[0][2 * p][1],     a[0], bbq[0], bbq[1]);
                mma_f16(acc[0][2 * p + 1][0], acc[0][2 * p + 1][1], a[0], bbq[2], bbq[3]);
                mma_f16(acc[1][2 * p][0],     acc[1][2 * p][1],     a[1], bbq[0], bbq[1]);
                mma_f16(acc[1][2 * p + 1][0], acc[1][2 * p + 1][1], a[1], bbq[2], bbq[3]);
            }
        }

        __syncthreads();         // all warps done reading buf
        if (ti + 2 < ntiles) load_b(buf, t + 2 * NSPLIT);
        cp_commit();             // always commit (keeps wait<1> bookkeeping exact)

        // ---- epilogue: acc == -0.5*LB; HMAX2 screen, cold exact fixup ----
        const int n0 = t * BN;
        #pragma unroll
        for (int mi = 0; mi < 2; mi++) {
            #pragma unroll
            for (int h = 0; h < 2; h++) {
                __half2 m = *reinterpret_cast<__half2*>(&acc[mi][h]);
                // NOTE: acc[mi][h] above is wrong indexing; do explicit chain:
                m = *reinterpret_cast<__half2*>(&acc[mi][0][h]);
                #pragma unroll
                for (int ni = 1; ni < 8; ni++)
                    m = __hmax2(m, *reinterpret_cast<__half2*>(&acc[mi][ni][h]));
                m = __hmax2(m, __lowhigh2highlow(m));
                if (__builtin_expect(__low2float(m) > TACC, 0)) {
                    const int row = bm0 + wm * 32 + mi * 16 + (lane >> 2) + 8 * h;
                    const float* xr = xp + (size_t)row * D_DIM;
                    #pragma unroll
                    for (int ni = 0; ni < 8; ni++) {
                        float2 c = __half22float2(
                            *reinterpret_cast<__half2*>(&acc[mi][ni][h]));
                        const int col = n0 + wn * 64 + ni * 8 + 2 * (lane & 3);
                        if (c.x > TACC) {
                            float d2 = exact_sqdist(xr, sp + (size_t)col * D_DIM);
                            rsum[mi][h] += __expf(-0.5f * d2) * g_w[col];
                        }
                        if (c.y > TACC) {
                            float d2 = exact_sqdist(xr, sp + (size_t)(col + 1) * D_DIM);
                            rsum[mi][h] += __expf(-0.5f * d2) * g_w[col + 1];
                        }
                    }
                }
            }
        }
    }

    // ---- row reduction: shfl within quad, one atomic per row per CTA ----
    #pragma unroll
    for (int mi = 0; mi < 2; mi++) {
        #pragma unroll
        for (int h = 0; h < 2; h++) {
            float v = rsum[mi][h];
            v += __shfl_xor_sync(0xffffffffu, v, 1);
            v += __shfl_xor_sync(0xffffffffu, v, 2);
            if ((lane & 3) == 0) {
                int r = bm0 + wm * 32 + mi * 16 + (lane >> 2) + h * 8;
                atomicAdd(&g_acc[r], v);
            }
        }
    }

    // ---- folded finalize: last CTA applies tanh(acc + b) ----
    __shared__ int s_last;
    __threadfence();
    __syncthreads();
    if (tid == 0) {
        int old = atomicAdd(&g_done, 1);
        s_last = (old == TOTAL_CTAS - 1);
    }
    __syncthreads();
    if (s_last) {
        __threadfence();
        const float bv = bb[0];
        #pragma unroll
        for (int i = 0; i < B_ROWS / THREADS; i++) {
            int r = tid + i * THREADS;
            out[r] = tanhf(g_acc[r] + bv);
        }
        if (tid == 0) g_done = 0;   // self-reset for next graph replay
    }
}

// ---------------------------------------------------------------------------
extern "C" void kernel_launch(void* const* d_in, const int* in_sizes, int n_in,
                              void* d_out, int out_size) {
    const float* x      = (const float*)d_in[0];
    const float* ds     = (const float*)d_in[1];
    const float* labels = (const float*)d_in[2];
    const float* lam    = (const float*)d_in[3];
    const float* b      = (const float*)d_in[4];
    float* out = (float*)d_out;
    (void)in_sizes; (void)n_in; (void)out_size;

    cudaFuncSetAttribute(svm_main, cudaFuncAttributeMaxDynamicSharedMemorySize,
                         SMEM_BYTES);

    prep<<<(B_ROWS + N_PAD + 7) / 8, 256>>>(x, ds, labels, lam);

    dim3 grid(GRID_X, NSPLIT);
    svm_main<<<grid, THREADS, SMEM_BYTES>>>(x, ds, b, out);
}